// round 13
// baseline (speedup 1.0000x reference)
#include <cuda_runtime.h>
#include <math.h>

// Problem constants (setup_inputs is deterministic: B=512, K=4)
#define BATCH 512
#define TOPK 4
#define NCAPS 181
#define ICAPS 96
#define CDIM 16
#define A2 128           // 2 * num_antennas
#define MLPM (BATCH*TOPK) // 2048
#define CHUNK 64         // L2-resident batch chunk (u_hat slice = 71 MB < 126 MB L2)

// ---------------- scratch (device globals; no runtime allocation) -----------
__device__ float g_h1[BATCH*64*49];          // conv1 out
__device__ float g_h2[BATCH*128*36];         // conv2 out
__device__ float g_h3[BATCH*256*25];         // conv3 out
__device__ float g_u [BATCH*ICAPS*CDIM];     // squashed primary caps
__device__ float g_uhat[(size_t)NCAPS*BATCH*ICAPS*CDIM]; // 569 MB, layout [o][b][i][d]
__device__ float g_c1[NCAPS*ICAPS];          // iter-1 coupling (batch-independent)
__device__ float g_blog[BATCH*NCAPS*ICAPS];  // routing logits
__device__ float g_maxl[BATCH*ICAPS];
__device__ float g_sume[BATCH*ICAPS];
__device__ float g_x  [BATCH*NCAPS*CDIM];    // final v
__device__ float g_len[BATCH*NCAPS];         // unnormalized lengths
__device__ int   g_idx[BATCH*TOPK];
__device__ float g_f1[MLPM*1024];
__device__ float g_f2[MLPM*768];
__device__ float g_f3[MLPM*512];
__device__ float g_f4[MLPM*512];
__device__ float g_f5[MLPM*256];

__device__ __forceinline__ float gelu_exact(float v) {
    return 0.5f * v * (1.0f + erff(v * 0.70710678118654752440f));
}

// ---------------- conv stack -------------------------------------------------
__global__ void conv1_kernel(const float* __restrict__ x, const float* __restrict__ w,
                             const float* __restrict__ bias) {
    int b = blockIdx.x, t = threadIdx.x;
    __shared__ float ins[192];   // 3x8x8
    __shared__ float ws[768];    // 64x3x2x2
    if (t < 192) ins[t] = x[b*192 + t];
    for (int j = t; j < 768; j += 256) ws[j] = w[j];
    __syncthreads();
    for (int p = t; p < 64*49; p += 256) {
        int oc = p / 49, pos = p % 49, y = pos / 7, xx = pos % 7;
        float acc = bias[oc];
        #pragma unroll
        for (int ic = 0; ic < 3; ic++)
            #pragma unroll
            for (int ky = 0; ky < 2; ky++)
                #pragma unroll
                for (int kx = 0; kx < 2; kx++)
                    acc += ws[((oc*3+ic)*2+ky)*2+kx] * ins[ic*64 + (y+ky)*8 + xx+kx];
        g_h1[b*3136 + p] = gelu_exact(acc);
    }
}

// conv2: [B,64,7,7] -> [B,128,6,6]. One out-channel per thread, 2 images/block.
__global__ void conv2_kernel(const float* __restrict__ w, const float* __restrict__ bias) {
    int b0 = blockIdx.x * 2, t = threadIdx.x;       // 256 threads
    int img = t >> 7, oc = t & 127;
    __shared__ float ins[2][64*49];                 // 25.1 KB
    for (int j = t; j < 2*64*49; j += 256) ins[j/3136][j%3136] = g_h1[b0*3136 + j];
    __syncthreads();
    const float* inp = ins[img];
    float acc[36];
    {
        float bv = bias[oc];
        #pragma unroll
        for (int p = 0; p < 36; p++) acc[p] = bv;
    }
    const float4* wp4 = (const float4*)(w + oc*256);
    for (int ic = 0; ic < 64; ic++) {
        float4 wv = wp4[ic];
        const float* r = &inp[ic*49];
        #pragma unroll
        for (int y = 0; y < 6; y++)
            #pragma unroll
            for (int xx = 0; xx < 6; xx++)
                acc[y*6+xx] += wv.x*r[y*7+xx] + wv.y*r[y*7+xx+1]
                             + wv.z*r[y*7+xx+7] + wv.w*r[y*7+xx+8];
    }
    float* outp = &g_h2[(b0+img)*4608 + oc*36];
    #pragma unroll
    for (int p = 0; p < 36; p++) outp[p] = gelu_exact(acc[p]);
}

// conv3: [B,128,6,6] -> [B,256,5,5]. One out-channel per thread, 1 image/block.
__global__ void conv3_kernel(const float* __restrict__ w, const float* __restrict__ bias) {
    int b = blockIdx.x, oc = threadIdx.x;           // 256 threads
    __shared__ float ins[128*36];                   // 18 KB
    for (int j = oc; j < 128*36; j += 256) ins[j] = g_h2[b*4608 + j];
    __syncthreads();
    float acc[25];
    {
        float bv = bias[oc];
        #pragma unroll
        for (int p = 0; p < 25; p++) acc[p] = bv;
    }
    const float4* wp4 = (const float4*)(w + oc*512);
    for (int ic = 0; ic < 128; ic++) {
        float4 wv = wp4[ic];
        const float* r = &ins[ic*36];
        #pragma unroll
        for (int y = 0; y < 5; y++)
            #pragma unroll
            for (int xx = 0; xx < 5; xx++)
                acc[y*5+xx] += wv.x*r[y*6+xx] + wv.y*r[y*6+xx+1]
                             + wv.z*r[y*6+xx+6] + wv.w*r[y*6+xx+7];
    }
    float* outp = &g_h3[b*6400 + oc*25];
    #pragma unroll
    for (int p = 0; p < 25; p++) outp[p] = gelu_exact(acc[p]);
}

// primary caps: [B,256,5,5] -> [B,96,16] + squash. One caps-channel per thread, 1 img/block.
__global__ void pc_kernel(const float* __restrict__ w, const float* __restrict__ bias) {
    int b = blockIdx.x, oc = threadIdx.x;           // 96 threads
    __shared__ float ins[256*25];                   // 25.6 KB
    for (int j = oc; j < 256*25; j += 96) ins[j] = g_h3[b*6400 + j];
    __syncthreads();
    float acc[16];
    {
        float bv = bias[oc];
        #pragma unroll
        for (int p = 0; p < 16; p++) acc[p] = bv;
    }
    const float4* wp4 = (const float4*)(w + oc*1024);
    for (int ic = 0; ic < 256; ic++) {
        float4 wv = wp4[ic];
        const float* r = &ins[ic*25];
        #pragma unroll
        for (int y = 0; y < 4; y++)
            #pragma unroll
            for (int xx = 0; xx < 4; xx++)
                acc[y*4+xx] += wv.x*r[y*5+xx] + wv.y*r[y*5+xx+1]
                             + wv.z*r[y*5+xx+5] + wv.w*r[y*5+xx+6];
    }
    float n2 = 0.f;
    #pragma unroll
    for (int d = 0; d < 16; d++) n2 += acc[d]*acc[d];
    float n = sqrtf(n2);
    float sc = (1.0f - expf(-n)) / (n + 1e-8f);
    float* outp = &g_u[(b*96 + oc)*16];
    #pragma unroll
    for (int d = 0; d < 16; d++) outp[d] = acc[d] * sc;
}

// ---------------- capsule layer ---------------------------------------------
// c1[o,i] = softmax over o of caps_b (batch-independent)
__global__ void c1_kernel(const float* __restrict__ caps_b) {
    int i = threadIdx.x;   // 96 threads, 1 block
    float m = -INFINITY;
    for (int o = 0; o < NCAPS; o++) m = fmaxf(m, caps_b[o*ICAPS + i]);
    float s = 0.f;
    for (int o = 0; o < NCAPS; o++) s += expf(caps_b[o*ICAPS + i] - m);
    for (int o = 0; o < NCAPS; o++)
        g_c1[o*ICAPS + i] = expf(caps_b[o*ICAPS + i] - m) / s;
}

// u_hat[o,b,i,d] = sum_k W[o,i,d,k] * u[b,i,k] for one CHUNK of 64 batches.
// Grid (ICAPS/4, NCAPS): each block handles 4 i values x 64 b.
__global__ void einsum_kernel(const float* __restrict__ W, int b0) {
    int iq = blockIdx.x, o = blockIdx.y;
    int i0 = iq*4;
    __shared__ float Wt[4][256];     // transposed: Wt[ii][k*16+d] = W[o,i0+ii,d,k]
    __shared__ float usm[4][64*17];
    int t = threadIdx.x;             // 256
    #pragma unroll
    for (int ii = 0; ii < 4; ii++) {
        float wv = W[((size_t)(o*ICAPS + i0+ii))*256 + t];   // t = d*16 + k
        Wt[ii][(t & 15)*16 + (t >> 4)] = wv;
    }
    #pragma unroll
    for (int r = 0; r < 16; r++) {
        int idx = t + r*256;          // 0..4095 over (bb, ii, k)
        int bb = idx >> 6, rem = idx & 63, ii = rem >> 4, k = rem & 15;
        usm[ii][bb*17 + k] = g_u[((b0+bb)*ICAPS + i0+ii)*CDIM + k];
    }
    __syncthreads();
    int dq = t & 3, bb = t >> 2;
    #pragma unroll
    for (int ii = 0; ii < 4; ii++) {
        float4 acc = make_float4(0.f, 0.f, 0.f, 0.f);
        #pragma unroll
        for (int k = 0; k < 16; k++) {
            float4 w4 = *(const float4*)&Wt[ii][k*16 + dq*4];
            float uv = usm[ii][bb*17 + k];
            acc.x += w4.x*uv; acc.y += w4.y*uv; acc.z += w4.z*uv; acc.w += w4.w*uv;
        }
        size_t off = (((size_t)o*BATCH + (b0+bb))*ICAPS + i0+ii)*CDIM + dq*4;
        *(float4*)&g_uhat[off] = acc;
    }
}

// per (b,i): online max + sumexp over the 181 out-caps (softmax axis=1)
__global__ void stats_kernel(int b0) {
    int b = b0 + blockIdx.x, i = threadIdx.x;  // 96 threads
    float m = -INFINITY, s = 0.f;
    for (int o = 0; o < NCAPS; o++) {
        float v = g_blog[((size_t)b*NCAPS + o)*ICAPS + i];
        if (v > m) { s = s * expf(m - v) + 1.f; m = v; }
        else       { s += expf(v - m); }
    }
    g_maxl[b*96 + i] = m;
    g_sume[b*96 + i] = s;
}

// one routing step for one (b,o); u_hat read is L2-hot within the chunk.
// mode 0: iter1 — c from g_c1, logits based on caps_b
// mode 1: iter2 — c from softmax(blog) via stats, update blog
// mode 2: iter3 — c from softmax(blog) via stats, emit x & len
__global__ void route_kernel(const float* __restrict__ caps_b, int mode, int b0) {
    int o = blockIdx.x, b = b0 + blockIdx.y, t = threadIdx.x;  // 128 threads
    __shared__ float csm[96];
    __shared__ float oldl[96];
    __shared__ float uhsm[96*17];
    __shared__ float red[128];
    __shared__ float ssm[16];
    __shared__ float sc_sm, n_sm;
    if (t < 96) {
        float cval, lv;
        if (mode == 0) {
            cval = g_c1[o*ICAPS + t];
            lv = caps_b[o*ICAPS + t];
        } else {
            lv = g_blog[((size_t)b*NCAPS + o)*ICAPS + t];
            cval = expf(lv - g_maxl[b*96 + t]) / g_sume[b*96 + t];
        }
        csm[t] = cval;
        oldl[t] = lv;
        const float4* uh = (const float4*)&g_uhat[(((size_t)o*BATCH + b)*ICAPS + t)*CDIM];
        float4 q0 = uh[0], q1 = uh[1], q2 = uh[2], q3 = uh[3];
        float* dst = &uhsm[t*17];
        dst[0]=q0.x; dst[1]=q0.y; dst[2]=q0.z; dst[3]=q0.w;
        dst[4]=q1.x; dst[5]=q1.y; dst[6]=q1.z; dst[7]=q1.w;
        dst[8]=q2.x; dst[9]=q2.y; dst[10]=q2.z; dst[11]=q2.w;
        dst[12]=q3.x; dst[13]=q3.y; dst[14]=q3.z; dst[15]=q3.w;
    }
    __syncthreads();
    int k = t & 15, part = t >> 4;  // 8 partials per k
    float partial = 0.f;
    for (int i = part; i < 96; i += 8) partial += csm[i] * uhsm[i*17 + k];
    red[part*16 + k] = partial;
    __syncthreads();
    if (t < 16) {
        float s = 0.f;
        #pragma unroll
        for (int p = 0; p < 8; p++) s += red[p*16 + t];
        ssm[t] = s;
    }
    __syncthreads();
    if (t == 0) {
        float n2 = 0.f;
        #pragma unroll
        for (int kk = 0; kk < 16; kk++) n2 += ssm[kk]*ssm[kk];
        float n = sqrtf(n2);
        sc_sm = (1.0f - expf(-n)) / (n + 1e-8f);
        n_sm = n;
    }
    __syncthreads();
    if (mode != 2) {
        if (t < 96) {
            float dot = 0.f;
            #pragma unroll
            for (int kk = 0; kk < 16; kk++) dot += ssm[kk] * uhsm[t*17 + kk];
            g_blog[((size_t)b*NCAPS + o)*ICAPS + t] = oldl[t] + sc_sm * dot;
        }
    } else {
        if (t < 16) g_x[((size_t)b*NCAPS + o)*CDIM + t] = ssm[t] * sc_sm;
        if (t == 0) g_len[b*NCAPS + o] = n_sm * sc_sm;
    }
}

// ---------------- peak picking ----------------------------------------------
__global__ void peak_kernel(float* __restrict__ out_len) {
    int b = blockIdx.x, t = threadIdx.x;  // 256 threads
    __shared__ float nl[NCAPS];
    __shared__ float pk[NCAPS];
    __shared__ float ssum;
    if (t < NCAPS) nl[t] = g_len[b*NCAPS + t];
    __syncthreads();
    if (t == 0) {
        float s = 0.f;
        for (int o = 0; o < NCAPS; o++) s += nl[o];
        ssum = s + 1e-8f;
    }
    __syncthreads();
    if (t < NCAPS) {
        float v = nl[t] / ssum;
        nl[t] = v;
        out_len[b*NCAPS + t] = v;
    }
    __syncthreads();
    if (t < NCAPS) {
        int lo = t - 5; if (lo < 0) lo = 0;
        int hi = t + 5; if (hi > NCAPS-1) hi = NCAPS-1;
        float m = -INFINITY;
        for (int j = lo; j <= hi; j++) m = fmaxf(m, nl[j]);
        pk[t] = (nl[t] == m) ? nl[t] : 0.f;
    }
    __syncthreads();
    if (t == 0) {
        int chosen[TOPK];
        for (int kk = 0; kk < TOPK; kk++) {
            float best = -INFINITY; int bi = 0;
            for (int j = 0; j < NCAPS; j++)
                if (pk[j] > best) { best = pk[j]; bi = j; }
            chosen[kk] = bi;
            pk[bi] = -INFINITY;
        }
        for (int a = 0; a < TOPK-1; a++)
            for (int c = 0; c < TOPK-1-a; c++)
                if (chosen[c] > chosen[c+1]) { int tmp = chosen[c]; chosen[c] = chosen[c+1]; chosen[c+1] = tmp; }
        for (int kk = 0; kk < TOPK; kk++) g_idx[b*TOPK + kk] = chosen[kk];
    }
}

// ---------------- MLP --------------------------------------------------------
// fc1 exploits one-hot sparsity: only rows [idx*16, idx*16+16) of fc1_w matter.
__global__ void fc1_kernel(const float* __restrict__ w, const float* __restrict__ bias) {
    int r = blockIdx.x, t = threadIdx.x;  // 256 threads, r in [0,2048)
    int b = r >> 2;
    int idx = g_idx[r];
    __shared__ float xf[16];
    if (t < 16) xf[t] = g_x[(b*NCAPS + idx)*CDIM + t];
    __syncthreads();
    for (int j = t; j < 1024; j += 256) {
        float acc = bias[j];
        #pragma unroll
        for (int d = 0; d < 16; d++) acc += xf[d] * w[(idx*16 + d)*1024 + j];
        g_f1[r*1024 + j] = gelu_exact(acc);
    }
}

// 128x64 tiled SGEMM, double-buffered (1 sync per K-step, LDG overlapped).
// C = act(A[M,K] @ B[K,N] + bias). M%128==0, N%64==0, K%16==0.
__global__ void sgemm_kernel(const float* __restrict__ A, const float* __restrict__ Bw,
                             const float* __restrict__ bias, float* __restrict__ C,
                             int M, int N, int K, int apply_gelu, int trans_head) {
    __shared__ float As[2][16][132];
    __shared__ float Bs[2][16][68];
    int tid = threadIdx.x;                  // 256 threads
    int tm = tid >> 4, tn = tid & 15;
    int rowBase = blockIdx.y * 128;
    int colBase = blockIdx.x * 64;
    float acc[8][4];
    {
        float bv[4];
        #pragma unroll
        for (int j = 0; j < 4; j++) bv[j] = bias[colBase + tn*4 + j];
        #pragma unroll
        for (int i = 0; i < 8; i++)
            #pragma unroll
            for (int j = 0; j < 4; j++) acc[i][j] = bv[j];
    }
    int arow = tid >> 1, ak = (tid & 1) * 8;
    int brow = tid >> 4, bcol = (tid & 15) * 4;
    {
        const float* ap = &A[(size_t)(rowBase + arow)*K + ak];
        float4 a0 = *(const float4*)ap;
        float4 a1 = *(const float4*)(ap + 4);
        As[0][ak+0][arow] = a0.x; As[0][ak+1][arow] = a0.y; As[0][ak+2][arow] = a0.z; As[0][ak+3][arow] = a0.w;
        As[0][ak+4][arow] = a1.x; As[0][ak+5][arow] = a1.y; As[0][ak+6][arow] = a1.z; As[0][ak+7][arow] = a1.w;
        float4 bv = *(const float4*)&Bw[(size_t)brow*N + colBase + bcol];
        *(float4*)&Bs[0][brow][bcol] = bv;
    }
    __syncthreads();
    int buf = 0;
    for (int k0 = 0; k0 < K; k0 += 16) {
        int nk = k0 + 16;
        float4 na0, na1, nbv;
        if (nk < K) {
            const float* ap = &A[(size_t)(rowBase + arow)*K + nk + ak];
            na0 = *(const float4*)ap;
            na1 = *(const float4*)(ap + 4);
            nbv = *(const float4*)&Bw[(size_t)(nk + brow)*N + colBase + bcol];
        }
        #pragma unroll
        for (int kk = 0; kk < 16; kk++) {
            float4 b4 = *(const float4*)&Bs[buf][kk][tn*4];
            float4 a4 = *(const float4*)&As[buf][kk][tm*8];
            float4 a5 = *(const float4*)&As[buf][kk][tm*8+4];
            acc[0][0] += a4.x*b4.x; acc[0][1] += a4.x*b4.y; acc[0][2] += a4.x*b4.z; acc[0][3] += a4.x*b4.w;
            acc[1][0] += a4.y*b4.x; acc[1][1] += a4.y*b4.y; acc[1][2] += a4.y*b4.z; acc[1][3] += a4.y*b4.w;
            acc[2][0] += a4.z*b4.x; acc[2][1] += a4.z*b4.y; acc[2][2] += a4.z*b4.z; acc[2][3] += a4.z*b4.w;
            acc[3][0] += a4.w*b4.x; acc[3][1] += a4.w*b4.y; acc[3][2] += a4.w*b4.z; acc[3][3] += a4.w*b4.w;
            acc[4][0] += a5.x*b4.x; acc[4][1] += a5.x*b4.y; acc[4][2] += a5.x*b4.z; acc[4][3] += a5.x*b4.w;
            acc[5][0] += a5.y*b4.x; acc[5][1] += a5.y*b4.y; acc[5][2] += a5.y*b4.z; acc[5][3] += a5.y*b4.w;
            acc[6][0] += a5.z*b4.x; acc[6][1] += a5.z*b4.y; acc[6][2] += a5.z*b4.z; acc[6][3] += a5.z*b4.w;
            acc[7][0] += a5.w*b4.x; acc[7][1] += a5.w*b4.y; acc[7][2] += a5.w*b4.z; acc[7][3] += a5.w*b4.w;
        }
        if (nk < K) {
            int nb = buf ^ 1;
            As[nb][ak+0][arow] = na0.x; As[nb][ak+1][arow] = na0.y; As[nb][ak+2][arow] = na0.z; As[nb][ak+3][arow] = na0.w;
            As[nb][ak+4][arow] = na1.x; As[nb][ak+5][arow] = na1.y; As[nb][ak+6][arow] = na1.z; As[nb][ak+7][arow] = na1.w;
            *(float4*)&Bs[nb][brow][bcol] = nbv;
        }
        __syncthreads();
        buf ^= 1;
    }
    #pragma unroll
    for (int i = 0; i < 8; i++) {
        int r = rowBase + tm*8 + i;
        #pragma unroll
        for (int j = 0; j < 4; j++) {
            int n = colBase + tn*4 + j;
            float v = acc[i][j];
            if (apply_gelu) v = gelu_exact(v);
            if (!trans_head) C[(size_t)r*N + n] = v;
            else {
                int b = r >> 2, kk = r & 3;
                C[(b*A2 + n)*TOPK + kk] = v;   // W_out[b, a, k]
            }
        }
    }
}

// ---------------- launcher ---------------------------------------------------
extern "C" void kernel_launch(void* const* d_in, const int* in_sizes, int n_in,
                              void* d_out, int out_size) {
    const float* scm     = (const float*)d_in[0];
    const float* conv1_w = (const float*)d_in[2];
    const float* conv1_b = (const float*)d_in[3];
    const float* conv2_w = (const float*)d_in[4];
    const float* conv2_b = (const float*)d_in[5];
    const float* conv3_w = (const float*)d_in[6];
    const float* conv3_b = (const float*)d_in[7];
    const float* pc_w    = (const float*)d_in[8];
    const float* pc_b    = (const float*)d_in[9];
    const float* caps_W  = (const float*)d_in[10];
    const float* caps_b  = (const float*)d_in[11];
    const float* fc1_w   = (const float*)d_in[12];
    const float* fc1_b   = (const float*)d_in[13];
    const float* fc2_w   = (const float*)d_in[14];
    const float* fc2_b   = (const float*)d_in[15];
    const float* fc3_w   = (const float*)d_in[16];
    const float* fc3_b   = (const float*)d_in[17];
    const float* fc4_w   = (const float*)d_in[18];
    const float* fc4_b   = (const float*)d_in[19];
    const float* fc5_w   = (const float*)d_in[20];
    const float* fc5_b   = (const float*)d_in[21];
    const float* head_w  = (const float*)d_in[22];
    const float* head_b  = (const float*)d_in[23];
    float* out = (float*)d_out;

    // conv stack
    conv1_kernel<<<BATCH, 256>>>(scm, conv1_w, conv1_b);
    conv2_kernel<<<BATCH/2, 256>>>(conv2_w, conv2_b);
    conv3_kernel<<<BATCH, 256>>>(conv3_w, conv3_b);
    pc_kernel<<<BATCH, 96>>>(pc_w, pc_b);

    // capsule layer, processed in L2-resident batch chunks (71 MB u_hat slice each)
    c1_kernel<<<1, 96>>>(caps_b);
    for (int b0 = 0; b0 < BATCH; b0 += CHUNK) {
        einsum_kernel<<<dim3(ICAPS/4, NCAPS), 256>>>(caps_W, b0);
        route_kernel<<<dim3(NCAPS, CHUNK), 128>>>(caps_b, 0, b0);   // iter1 (c1)
        stats_kernel<<<CHUNK, 96>>>(b0);
        route_kernel<<<dim3(NCAPS, CHUNK), 128>>>(caps_b, 1, b0);   // iter2
        stats_kernel<<<CHUNK, 96>>>(b0);
        route_kernel<<<dim3(NCAPS, CHUNK), 128>>>(caps_b, 2, b0);   // iter3 (emit)
    }

    // peaks + length output (length lives after W_out in d_out)
    float* out_len = out + BATCH * A2 * TOPK;
    peak_kernel<<<BATCH, 256>>>(out_len);

    // MLP
    float* g_f1p; cudaGetSymbolAddress((void**)&g_f1p, g_f1);
    float* g_f2p; cudaGetSymbolAddress((void**)&g_f2p, g_f2);
    float* g_f3p; cudaGetSymbolAddress((void**)&g_f3p, g_f3);
    float* g_f4p; cudaGetSymbolAddress((void**)&g_f4p, g_f4);
    float* g_f5p; cudaGetSymbolAddress((void**)&g_f5p, g_f5);

    fc1_kernel<<<MLPM, 256>>>(fc1_w, fc1_b);
    sgemm_kernel<<<dim3(768/64, MLPM/128), 256>>>(g_f1p, fc2_w, fc2_b, g_f2p, MLPM, 768, 1024, 1, 0);
    sgemm_kernel<<<dim3(512/64, MLPM/128), 256>>>(g_f2p, fc3_w, fc3_b, g_f3p, MLPM, 512,  768, 1, 0);
    sgemm_kernel<<<dim3(512/64, MLPM/128), 256>>>(g_f3p, fc4_w, fc4_b, g_f4p, MLPM, 512,  512, 1, 0);
    sgemm_kernel<<<dim3(256/64, MLPM/128), 256>>>(g_f4p, fc5_w, fc5_b, g_f5p, MLPM, 256,  512, 1, 0);
    sgemm_kernel<<<dim3(128/64, MLPM/128), 256>>>(g_f5p, head_w, head_b, out,  MLPM, 128,  256, 0, 1);
    (void)in_sizes; (void)n_in; (void)out_size;
}

// round 14
// speedup vs baseline: 1.4338x; 1.4338x over previous
#include <cuda_runtime.h>
#include <math.h>

// Problem constants (setup_inputs is deterministic: B=512, K=4)
#define BATCH 512
#define TOPK 4
#define NCAPS 181
#define ICAPS 96
#define CDIM 16
#define A2 128           // 2 * num_antennas
#define MLPM (BATCH*TOPK) // 2048

// ---------------- scratch (device globals; no runtime allocation) -----------
__device__ float g_h1[BATCH*64*49];          // conv1 out
__device__ float g_h2[BATCH*128*36];         // conv2 out
__device__ float g_h3[BATCH*256*25];         // conv3 out
__device__ float g_u [BATCH*ICAPS*CDIM];     // squashed primary caps
__device__ float g_uhat[(size_t)NCAPS*BATCH*ICAPS*CDIM]; // 569 MB, layout [o][b][i][d]
__device__ float g_c1[NCAPS*ICAPS];          // iter-1 coupling (batch-independent)
__device__ float g_blog[BATCH*NCAPS*ICAPS];  // routing logits
__device__ float g_maxl[BATCH*ICAPS];
__device__ float g_sume[BATCH*ICAPS];
__device__ float g_x  [BATCH*NCAPS*CDIM];    // final v
__device__ float g_len[BATCH*NCAPS];         // unnormalized lengths
__device__ int   g_idx[BATCH*TOPK];
__device__ float g_f1[MLPM*1024];
__device__ float g_f2[MLPM*768];
__device__ float g_f3[MLPM*512];
__device__ float g_f4[MLPM*512];
__device__ float g_f5[MLPM*256];

__device__ __forceinline__ float gelu_exact(float v) {
    return 0.5f * v * (1.0f + erff(v * 0.70710678118654752440f));
}

// ---------------- conv stack -------------------------------------------------
__global__ void conv1_kernel(const float* __restrict__ x, const float* __restrict__ w,
                             const float* __restrict__ bias) {
    int b = blockIdx.x, t = threadIdx.x;
    __shared__ float ins[192];   // 3x8x8
    __shared__ float ws[768];    // 64x3x2x2
    if (t < 192) ins[t] = x[b*192 + t];
    for (int j = t; j < 768; j += 256) ws[j] = w[j];
    __syncthreads();
    for (int p = t; p < 64*49; p += 256) {
        int oc = p / 49, pos = p % 49, y = pos / 7, xx = pos % 7;
        float acc = bias[oc];
        #pragma unroll
        for (int ic = 0; ic < 3; ic++)
            #pragma unroll
            for (int ky = 0; ky < 2; ky++)
                #pragma unroll
                for (int kx = 0; kx < 2; kx++)
                    acc += ws[((oc*3+ic)*2+ky)*2+kx] * ins[ic*64 + (y+ky)*8 + xx+kx];
        g_h1[b*3136 + p] = gelu_exact(acc);
    }
}

// conv2: [B,64,7,7] -> [B,128,6,6]. One out-channel per thread, 2 images/block.
__global__ void conv2_kernel(const float* __restrict__ w, const float* __restrict__ bias) {
    int b0 = blockIdx.x * 2, t = threadIdx.x;       // 256 threads
    int img = t >> 7, oc = t & 127;
    __shared__ float ins[2][64*49];                 // 25.1 KB
    for (int j = t; j < 2*64*49; j += 256) ins[j/3136][j%3136] = g_h1[b0*3136 + j];
    __syncthreads();
    const float* inp = ins[img];
    float acc[36];
    {
        float bv = bias[oc];
        #pragma unroll
        for (int p = 0; p < 36; p++) acc[p] = bv;
    }
    const float4* wp4 = (const float4*)(w + oc*256);
    for (int ic = 0; ic < 64; ic++) {
        float4 wv = wp4[ic];
        const float* r = &inp[ic*49];
        #pragma unroll
        for (int y = 0; y < 6; y++)
            #pragma unroll
            for (int xx = 0; xx < 6; xx++)
                acc[y*6+xx] += wv.x*r[y*7+xx] + wv.y*r[y*7+xx+1]
                             + wv.z*r[y*7+xx+7] + wv.w*r[y*7+xx+8];
    }
    float* outp = &g_h2[(b0+img)*4608 + oc*36];
    #pragma unroll
    for (int p = 0; p < 36; p++) outp[p] = gelu_exact(acc[p]);
}

// conv3: [B,128,6,6] -> [B,256,5,5]. One out-channel per thread, 1 image/block.
__global__ void conv3_kernel(const float* __restrict__ w, const float* __restrict__ bias) {
    int b = blockIdx.x, oc = threadIdx.x;           // 256 threads
    __shared__ float ins[128*36];                   // 18 KB
    for (int j = oc; j < 128*36; j += 256) ins[j] = g_h2[b*4608 + j];
    __syncthreads();
    float acc[25];
    {
        float bv = bias[oc];
        #pragma unroll
        for (int p = 0; p < 25; p++) acc[p] = bv;
    }
    const float4* wp4 = (const float4*)(w + oc*512);
    for (int ic = 0; ic < 128; ic++) {
        float4 wv = wp4[ic];
        const float* r = &ins[ic*36];
        #pragma unroll
        for (int y = 0; y < 5; y++)
            #pragma unroll
            for (int xx = 0; xx < 5; xx++)
                acc[y*5+xx] += wv.x*r[y*6+xx] + wv.y*r[y*6+xx+1]
                             + wv.z*r[y*6+xx+6] + wv.w*r[y*6+xx+7];
    }
    float* outp = &g_h3[b*6400 + oc*25];
    #pragma unroll
    for (int p = 0; p < 25; p++) outp[p] = gelu_exact(acc[p]);
}

// primary caps: [B,256,5,5] -> [B,96,16] + squash. One caps-channel per thread, 1 img/block.
__global__ void pc_kernel(const float* __restrict__ w, const float* __restrict__ bias) {
    int b = blockIdx.x, oc = threadIdx.x;           // 96 threads
    __shared__ float ins[256*25];                   // 25.6 KB
    for (int j = oc; j < 256*25; j += 96) ins[j] = g_h3[b*6400 + j];
    __syncthreads();
    float acc[16];
    {
        float bv = bias[oc];
        #pragma unroll
        for (int p = 0; p < 16; p++) acc[p] = bv;
    }
    const float4* wp4 = (const float4*)(w + oc*1024);
    for (int ic = 0; ic < 256; ic++) {
        float4 wv = wp4[ic];
        const float* r = &ins[ic*25];
        #pragma unroll
        for (int y = 0; y < 4; y++)
            #pragma unroll
            for (int xx = 0; xx < 4; xx++)
                acc[y*4+xx] += wv.x*r[y*5+xx] + wv.y*r[y*5+xx+1]
                             + wv.z*r[y*5+xx+5] + wv.w*r[y*5+xx+6];
    }
    float n2 = 0.f;
    #pragma unroll
    for (int d = 0; d < 16; d++) n2 += acc[d]*acc[d];
    float n = sqrtf(n2);
    float sc = (1.0f - expf(-n)) / (n + 1e-8f);
    float* outp = &g_u[(b*96 + oc)*16];
    #pragma unroll
    for (int d = 0; d < 16; d++) outp[d] = acc[d] * sc;
}

// ---------------- capsule layer ---------------------------------------------
// c1[o,i] = softmax over o of caps_b (batch-independent)
__global__ void c1_kernel(const float* __restrict__ caps_b) {
    int i = threadIdx.x;   // 96 threads, 1 block
    float m = -INFINITY;
    for (int o = 0; o < NCAPS; o++) m = fmaxf(m, caps_b[o*ICAPS + i]);
    float s = 0.f;
    for (int o = 0; o < NCAPS; o++) s += expf(caps_b[o*ICAPS + i] - m);
    for (int o = 0; o < NCAPS; o++)
        g_c1[o*ICAPS + i] = expf(caps_b[o*ICAPS + i] - m) / s;
}

// u_hat[o,b,i,d] = sum_k W[o,i,d,k] * u[b,i,k]   (o-major layout)
__global__ void einsum_kernel(const float* __restrict__ W) {
    int i = blockIdx.x, o = blockIdx.y;
    __shared__ float Wt[256];    // transposed: Wt[k*16+d] = W[d*16+k]
    __shared__ float usm[64*17];
    int t = threadIdx.x;
    float wv = W[(o*96 + i)*256 + t];   // t = d*16 + k
    Wt[(t & 15)*16 + (t >> 4)] = wv;
    __syncthreads();
    int dq = t & 3, bb = t >> 2;
    float4 wreg[16];   // wreg[k] = {W[dq*4+0..3, k]}
    #pragma unroll
    for (int k = 0; k < 16; k++) wreg[k] = *(const float4*)&Wt[k*16 + dq*4];
    for (int b0 = 0; b0 < BATCH; b0 += 64) {
        __syncthreads();
        #pragma unroll
        for (int r = 0; r < 4; r++) {
            int idx = t + r*256;
            int bb2 = idx >> 4, k2 = idx & 15;
            usm[bb2*17 + k2] = g_u[((b0+bb2)*96 + i)*16 + k2];
        }
        __syncthreads();
        float4 acc = make_float4(0.f, 0.f, 0.f, 0.f);
        #pragma unroll
        for (int k = 0; k < 16; k++) {
            float uv = usm[bb*17 + k];
            acc.x += wreg[k].x * uv; acc.y += wreg[k].y * uv;
            acc.z += wreg[k].z * uv; acc.w += wreg[k].w * uv;
        }
        size_t off = (((size_t)o*BATCH + (b0+bb))*ICAPS + i)*CDIM + dq*4;
        *(float4*)&g_uhat[off] = acc;
    }
}

// per (b,i): online max + sumexp over the 181 out-caps (softmax axis=1)
__global__ void stats_kernel() {
    int b = blockIdx.x, i = threadIdx.x;  // 96 threads
    float m = -INFINITY, s = 0.f;
    for (int o = 0; o < NCAPS; o++) {
        float v = g_blog[(b*NCAPS + o)*ICAPS + i];
        if (v > m) { s = s * expf(m - v) + 1.f; m = v; }
        else       { s += expf(v - m); }
    }
    g_maxl[b*96 + i] = m;
    g_sume[b*96 + i] = s;
}

// one routing step for one (b,o): c -> weighted sum -> squash -> (b update | emit v,len)
// mode 0: iter1 — c from g_c1, logits based on caps_b (no init_blog / stats needed)
// mode 1: iter2 — c from softmax(blog) via stats, update blog
// mode 2: iter3 — c from softmax(blog) via stats, emit x & len
__global__ void route_kernel(const float* __restrict__ caps_b, int mode) {
    int o = blockIdx.x, b = blockIdx.y, t = threadIdx.x;  // 128 threads
    __shared__ float csm[96];
    __shared__ float oldl[96];
    __shared__ float uhsm[96*17];
    __shared__ float red[128];
    __shared__ float ssm[16];
    __shared__ float sc_sm, n_sm;
    if (t < 96) {
        float cval, lv;
        if (mode == 0) {
            cval = g_c1[o*ICAPS + t];
            lv = caps_b[o*ICAPS + t];
        } else {
            lv = g_blog[(b*NCAPS + o)*ICAPS + t];
            cval = expf(lv - g_maxl[b*96 + t]) / g_sume[b*96 + t];
        }
        csm[t] = cval;
        oldl[t] = lv;
        const float4* uh = (const float4*)&g_uhat[(((size_t)o*BATCH + b)*ICAPS + t)*CDIM];
        float4 q0 = uh[0], q1 = uh[1], q2 = uh[2], q3 = uh[3];
        float* dst = &uhsm[t*17];
        dst[0]=q0.x; dst[1]=q0.y; dst[2]=q0.z; dst[3]=q0.w;
        dst[4]=q1.x; dst[5]=q1.y; dst[6]=q1.z; dst[7]=q1.w;
        dst[8]=q2.x; dst[9]=q2.y; dst[10]=q2.z; dst[11]=q2.w;
        dst[12]=q3.x; dst[13]=q3.y; dst[14]=q3.z; dst[15]=q3.w;
    }
    __syncthreads();
    int k = t & 15, part = t >> 4;  // 8 partials per k
    float partial = 0.f;
    for (int i = part; i < 96; i += 8) partial += csm[i] * uhsm[i*17 + k];
    red[part*16 + k] = partial;
    __syncthreads();
    if (t < 16) {
        float s = 0.f;
        #pragma unroll
        for (int p = 0; p < 8; p++) s += red[p*16 + t];
        ssm[t] = s;
    }
    __syncthreads();
    if (t == 0) {
        float n2 = 0.f;
        #pragma unroll
        for (int kk = 0; kk < 16; kk++) n2 += ssm[kk]*ssm[kk];
        float n = sqrtf(n2);
        sc_sm = (1.0f - expf(-n)) / (n + 1e-8f);
        n_sm = n;
    }
    __syncthreads();
    if (mode != 2) {
        if (t < 96) {
            float dot = 0.f;
            #pragma unroll
            for (int kk = 0; kk < 16; kk++) dot += ssm[kk] * uhsm[t*17 + kk];
            g_blog[(b*NCAPS + o)*ICAPS + t] = oldl[t] + sc_sm * dot;
        }
    } else {
        if (t < 16) g_x[(b*NCAPS + o)*CDIM + t] = ssm[t] * sc_sm;
        if (t == 0) g_len[b*NCAPS + o] = n_sm * sc_sm;
    }
}

// ---------------- peak picking ----------------------------------------------
__global__ void peak_kernel(float* __restrict__ out_len) {
    int b = blockIdx.x, t = threadIdx.x;  // 256 threads
    __shared__ float nl[NCAPS];
    __shared__ float pk[NCAPS];
    __shared__ float ssum;
    if (t < NCAPS) nl[t] = g_len[b*NCAPS + t];
    __syncthreads();
    if (t == 0) {
        float s = 0.f;
        for (int o = 0; o < NCAPS; o++) s += nl[o];
        ssum = s + 1e-8f;
    }
    __syncthreads();
    if (t < NCAPS) {
        float v = nl[t] / ssum;
        nl[t] = v;
        out_len[b*NCAPS + t] = v;
    }
    __syncthreads();
    if (t < NCAPS) {
        int lo = t - 5; if (lo < 0) lo = 0;
        int hi = t + 5; if (hi > NCAPS-1) hi = NCAPS-1;
        float m = -INFINITY;
        for (int j = lo; j <= hi; j++) m = fmaxf(m, nl[j]);
        pk[t] = (nl[t] == m) ? nl[t] : 0.f;
    }
    __syncthreads();
    if (t == 0) {
        int chosen[TOPK];
        for (int kk = 0; kk < TOPK; kk++) {
            float best = -INFINITY; int bi = 0;
            for (int j = 0; j < NCAPS; j++)
                if (pk[j] > best) { best = pk[j]; bi = j; }
            chosen[kk] = bi;
            pk[bi] = -INFINITY;
        }
        for (int a = 0; a < TOPK-1; a++)
            for (int c = 0; c < TOPK-1-a; c++)
                if (chosen[c] > chosen[c+1]) { int tmp = chosen[c]; chosen[c] = chosen[c+1]; chosen[c+1] = tmp; }
        for (int kk = 0; kk < TOPK; kk++) g_idx[b*TOPK + kk] = chosen[kk];
    }
}

// ---------------- MLP --------------------------------------------------------
// fc1 exploits one-hot sparsity: only rows [idx*16, idx*16+16) of fc1_w matter.
__global__ void fc1_kernel(const float* __restrict__ w, const float* __restrict__ bias) {
    int r = blockIdx.x, t = threadIdx.x;  // 256 threads, r in [0,2048)
    int b = r >> 2;
    int idx = g_idx[r];
    __shared__ float xf[16];
    if (t < 16) xf[t] = g_x[(b*NCAPS + idx)*CDIM + t];
    __syncthreads();
    for (int j = t; j < 1024; j += 256) {
        float acc = bias[j];
        #pragma unroll
        for (int d = 0; d < 16; d++) acc += xf[d] * w[(idx*16 + d)*1024 + j];
        g_f1[r*1024 + j] = gelu_exact(acc);
    }
}

// 64x64 tiled SGEMM (more blocks -> better SM occupancy for these small GEMMs),
// double-buffered (1 sync per K-step). C = act(A[M,K] @ B[K,N] + bias).
// M%64==0, N%64==0, K%16==0. trans_head: scatter-store as W_out[b, a, kk].
__global__ void sgemm_kernel(const float* __restrict__ A, const float* __restrict__ Bw,
                             const float* __restrict__ bias, float* __restrict__ C,
                             int M, int N, int K, int apply_gelu, int trans_head) {
    __shared__ float As[2][16][68];
    __shared__ float Bs[2][16][68];
    int tid = threadIdx.x;                  // 256 threads
    int tm = tid >> 4, tn = tid & 15;       // 4 rows x 4 cols per thread
    int rowBase = blockIdx.y * 64;
    int colBase = blockIdx.x * 64;
    float acc[4][4];
    {
        float bv[4];
        #pragma unroll
        for (int j = 0; j < 4; j++) bv[j] = bias[colBase + tn*4 + j];
        #pragma unroll
        for (int i = 0; i < 4; i++)
            #pragma unroll
            for (int j = 0; j < 4; j++) acc[i][j] = bv[j];
    }
    int arow = tid >> 2, ak = (tid & 3) * 4;   // A: 64 rows x 16 k, 1 float4/thread
    int brow = tid >> 4, bcol = (tid & 15) * 4;
    {
        float4 av = *(const float4*)&A[(size_t)(rowBase + arow)*K + ak];
        As[0][ak+0][arow] = av.x; As[0][ak+1][arow] = av.y;
        As[0][ak+2][arow] = av.z; As[0][ak+3][arow] = av.w;
        float4 bv = *(const float4*)&Bw[(size_t)brow*N + colBase + bcol];
        *(float4*)&Bs[0][brow][bcol] = bv;
    }
    __syncthreads();
    int buf = 0;
    for (int k0 = 0; k0 < K; k0 += 16) {
        int nk = k0 + 16;
        float4 nav, nbv;
        if (nk < K) {
            nav = *(const float4*)&A[(size_t)(rowBase + arow)*K + nk + ak];
            nbv = *(const float4*)&Bw[(size_t)(nk + brow)*N + colBase + bcol];
        }
        #pragma unroll
        for (int kk = 0; kk < 16; kk++) {
            float4 a4 = *(const float4*)&As[buf][kk][tm*4];
            float4 b4 = *(const float4*)&Bs[buf][kk][tn*4];
            acc[0][0] += a4.x*b4.x; acc[0][1] += a4.x*b4.y; acc[0][2] += a4.x*b4.z; acc[0][3] += a4.x*b4.w;
            acc[1][0] += a4.y*b4.x; acc[1][1] += a4.y*b4.y; acc[1][2] += a4.y*b4.z; acc[1][3] += a4.y*b4.w;
            acc[2][0] += a4.z*b4.x; acc[2][1] += a4.z*b4.y; acc[2][2] += a4.z*b4.z; acc[2][3] += a4.z*b4.w;
            acc[3][0] += a4.w*b4.x; acc[3][1] += a4.w*b4.y; acc[3][2] += a4.w*b4.z; acc[3][3] += a4.w*b4.w;
        }
        if (nk < K) {
            int nb = buf ^ 1;
            As[nb][ak+0][arow] = nav.x; As[nb][ak+1][arow] = nav.y;
            As[nb][ak+2][arow] = nav.z; As[nb][ak+3][arow] = nav.w;
            *(float4*)&Bs[nb][brow][bcol] = nbv;
        }
        __syncthreads();
        buf ^= 1;
    }
    #pragma unroll
    for (int i = 0; i < 4; i++) {
        int r = rowBase + tm*4 + i;
        #pragma unroll
        for (int j = 0; j < 4; j++) {
            int n = colBase + tn*4 + j;
            float v = acc[i][j];
            if (apply_gelu) v = gelu_exact(v);
            if (!trans_head) C[(size_t)r*N + n] = v;
            else {
                int b = r >> 2, kk = r & 3;
                C[(b*A2 + n)*TOPK + kk] = v;   // W_out[b, a, k]
            }
        }
    }
}

// ---------------- launcher ---------------------------------------------------
extern "C" void kernel_launch(void* const* d_in, const int* in_sizes, int n_in,
                              void* d_out, int out_size) {
    const float* scm     = (const float*)d_in[0];
    const float* conv1_w = (const float*)d_in[2];
    const float* conv1_b = (const float*)d_in[3];
    const float* conv2_w = (const float*)d_in[4];
    const float* conv2_b = (const float*)d_in[5];
    const float* conv3_w = (const float*)d_in[6];
    const float* conv3_b = (const float*)d_in[7];
    const float* pc_w    = (const float*)d_in[8];
    const float* pc_b    = (const float*)d_in[9];
    const float* caps_W  = (const float*)d_in[10];
    const float* caps_b  = (const float*)d_in[11];
    const float* fc1_w   = (const float*)d_in[12];
    const float* fc1_b   = (const float*)d_in[13];
    const float* fc2_w   = (const float*)d_in[14];
    const float* fc2_b   = (const float*)d_in[15];
    const float* fc3_w   = (const float*)d_in[16];
    const float* fc3_b   = (const float*)d_in[17];
    const float* fc4_w   = (const float*)d_in[18];
    const float* fc4_b   = (const float*)d_in[19];
    const float* fc5_w   = (const float*)d_in[20];
    const float* fc5_b   = (const float*)d_in[21];
    const float* head_w  = (const float*)d_in[22];
    const float* head_b  = (const float*)d_in[23];
    float* out = (float*)d_out;

    // conv stack
    conv1_kernel<<<BATCH, 256>>>(scm, conv1_w, conv1_b);
    conv2_kernel<<<BATCH/2, 256>>>(conv2_w, conv2_b);
    conv3_kernel<<<BATCH, 256>>>(conv3_w, conv3_b);
    pc_kernel<<<BATCH, 96>>>(pc_w, pc_b);

    // capsule layer: c1 precompute kills init_blog + stats1 (R11 best config)
    c1_kernel<<<1, 96>>>(caps_b);
    einsum_kernel<<<dim3(ICAPS, NCAPS), 256>>>(caps_W);
    route_kernel<<<dim3(NCAPS, BATCH), 128>>>(caps_b, 0);   // iter1 (c1, base=caps_b)
    stats_kernel<<<BATCH, 96>>>();
    route_kernel<<<dim3(NCAPS, BATCH), 128>>>(caps_b, 1);   // iter2
    stats_kernel<<<BATCH, 96>>>();
    route_kernel<<<dim3(NCAPS, BATCH), 128>>>(caps_b, 2);   // iter3 (emit)

    // peaks + length output (length lives after W_out in d_out)
    float* out_len = out + BATCH * A2 * TOPK;
    peak_kernel<<<BATCH, 256>>>(out_len);

    // MLP (64x64 tiles -> 2-4x more blocks than 128x64; occupancy-driven)
    float* g_f1p; cudaGetSymbolAddress((void**)&g_f1p, g_f1);
    float* g_f2p; cudaGetSymbolAddress((void**)&g_f2p, g_f2);
    float* g_f3p; cudaGetSymbolAddress((void**)&g_f3p, g_f3);
    float* g_f4p; cudaGetSymbolAddress((void**)&g_f4p, g_f4);
    float* g_f5p; cudaGetSymbolAddress((void**)&g_f5p, g_f5);

    fc1_kernel<<<MLPM, 256>>>(fc1_w, fc1_b);
    sgemm_kernel<<<dim3(768/64, MLPM/64), 256>>>(g_f1p, fc2_w, fc2_b, g_f2p, MLPM, 768, 1024, 1, 0);
    sgemm_kernel<<<dim3(512/64, MLPM/64), 256>>>(g_f2p, fc3_w, fc3_b, g_f3p, MLPM, 512,  768, 1, 0);
    sgemm_kernel<<<dim3(512/64, MLPM/64), 256>>>(g_f3p, fc4_w, fc4_b, g_f4p, MLPM, 512,  512, 1, 0);
    sgemm_kernel<<<dim3(256/64, MLPM/64), 256>>>(g_f4p, fc5_w, fc5_b, g_f5p, MLPM, 256,  512, 1, 0);
    sgemm_kernel<<<dim3(128/64, MLPM/64), 256>>>(g_f5p, head_w, head_b, out,  MLPM, 128,  256, 0, 1);
    (void)in_sizes; (void)n_in; (void)out_size;
}